// round 15
// baseline (speedup 1.0000x reference)
#include <cuda_runtime.h>
#include <cuda_bf16.h>
#include <stdint.h>
#include <math.h>

#define BB 64
#define TT 8192
#define FIN 6
#define MODES 32
#define NLAYERS 4
#define NFC1 128
#define NOUT 7
#define KSPLIT 4
#define KCHUNK (TT / KSPLIT)      // 2048
#define NITER (KCHUNK / 64)       // 32
#define XELEMS (BB * TT * 64)

// ---------------- device globals ----------------
__device__ __nv_bfloat16 g_Fbf[128 * TT];   // rows 0-31 cos_hi, 32-63 (-sin)_hi, 64-95 cos_lo, 96-127 (-sin)_lo
__device__ __nv_bfloat16 g_Gh[TT * 64];     // irfft basis [t][j] hi
__device__ __nv_bfloat16 g_Gl[TT * 64];
__device__ __nv_bfloat16 g_xnh[2][XELEMS];  // x [b][t][c] hi, double buffered
__device__ __nv_bfloat16 g_xnl[2][XELEMS];
__device__ float g_Xp[KSPLIT * BB * 128 * 64];
__device__ __nv_bfloat16 g_Zh[BB * 64 * 64];
__device__ __nv_bfloat16 g_Zl[BB * 64 * 64];
__device__ __nv_bfloat16 g_cwh[NLAYERS * 64 * 64];
__device__ __nv_bfloat16 g_cwl[NLAYERS * 64 * 64];

// ---------------- helpers ----------------
__device__ __forceinline__ float gelu_exact(float v) {
    return 0.5f * v * (1.0f + erff(v * 0.70710678118654752440f));
}
__device__ __forceinline__ void bsplit(float v, __nv_bfloat16& h, __nv_bfloat16& l) {
    h = __float2bfloat16(v);
    l = __float2bfloat16(v - __bfloat162float(h));
}
__device__ __forceinline__ uint32_t smem_u32(const void* p) {
    uint32_t a;
    asm("{ .reg .u64 t; cvta.to.shared.u64 t, %1; cvt.u32.u64 %0, t; }" : "=r"(a) : "l"(p));
    return a;
}
__device__ __forceinline__ void cpa16(uint32_t s, const void* g) {
    asm volatile("cp.async.cg.shared.global [%0], [%1], 16;" :: "r"(s), "l"(g));
}
#define CP_COMMIT() asm volatile("cp.async.commit_group;" ::: "memory")
#define CP_WAIT(n)  asm volatile("cp.async.wait_group %0;" :: "n"(n) : "memory")

__device__ __forceinline__ void ldmA(uint32_t* a, uint32_t addr) {
    asm volatile("ldmatrix.sync.aligned.m8n8.x4.shared.b16 {%0,%1,%2,%3}, [%4];"
                 : "=r"(a[0]), "=r"(a[1]), "=r"(a[2]), "=r"(a[3]) : "r"(addr));
}
__device__ __forceinline__ void ldmB4(uint32_t* b, uint32_t addr) {
    asm volatile("ldmatrix.sync.aligned.m8n8.x4.trans.shared.b16 {%0,%1,%2,%3}, [%4];"
                 : "=r"(b[0]), "=r"(b[1]), "=r"(b[2]), "=r"(b[3]) : "r"(addr));
}
__device__ __forceinline__ void mma16816(float* d, const uint32_t* a, const uint32_t* b) {
    asm volatile(
        "mma.sync.aligned.m16n8k16.row.col.f32.bf16.bf16.f32 "
        "{%0,%1,%2,%3}, {%4,%5,%6,%7}, {%8,%9}, {%0,%1,%2,%3};"
        : "+f"(d[0]), "+f"(d[1]), "+f"(d[2]), "+f"(d[3])
        : "r"(a[0]), "r"(a[1]), "r"(a[2]), "r"(a[3]), "r"(b[0]), "r"(b[1]));
}
// swizzled byte offset within a tile of 128B rows: chunk index ^= (row & 7)
__device__ __forceinline__ uint32_t swz(int row, int chunk) {
    return (uint32_t)(row * 128 + ((chunk ^ (row & 7)) << 4));
}

// ---------------------------------------------------------------------------
__global__ void twiddle_k() {
    int idx = blockIdx.x * blockDim.x + threadIdx.x;
    if (idx >= MODES * TT) return;
    int k = idx >> 13;
    int t = idx & (TT - 1);
    int m = (k * t) & (TT - 1);
    float ang = 2.0f * (float)m / (float)TT;
    float s, c;
    sincospif(ang, &s, &c);
    __nv_bfloat16 h, l;
    bsplit(c, h, l);
    g_Fbf[k * TT + t] = h;  g_Fbf[(64 + k) * TT + t] = l;
    g_Gh[t * 64 + k] = h;   g_Gl[t * 64 + k] = l;
    bsplit(-s, h, l);
    g_Fbf[(32 + k) * TT + t] = h;  g_Fbf[(96 + k) * TT + t] = l;
    bsplit(s, h, l);
    g_Gh[t * 64 + 32 + k] = h;  g_Gl[t * 64 + 32 + k] = l;
}

__global__ void cwprep(const float* __restrict__ convw) {
    int idx = blockIdx.x * blockDim.x + threadIdx.x;
    if (idx >= NLAYERS * 64 * 64) return;
    __nv_bfloat16 h, l;
    bsplit(convw[idx], h, l);
    g_cwh[idx] = h;
    g_cwl[idx] = l;
}

// ---------------------------------------------------------------------------
// fc0: 2 channels per thread, packed 32-bit stores
__global__ void __launch_bounds__(256) fc0_bf(const float* __restrict__ inp,
                                              const float* __restrict__ w,
                                              const float* __restrict__ bias,
                                              __nv_bfloat16* __restrict__ xnh,
                                              __nv_bfloat16* __restrict__ xnl) {
    __shared__ float sw[FIN * 64];
    __shared__ float sb[64];
    int tid = threadIdx.x;
    for (int i = tid; i < FIN * 64; i += 256) sw[i] = w[i];
    if (tid < 64) sb[tid] = bias[tid];
    __syncthreads();
    long gid = (long)blockIdx.x * 256 + tid;         // over B*T*32
    int c2 = (int)(gid & 31) * 2;
    long bt = gid >> 5;
    const float* ip = inp + bt * FIN;
    float a0 = sb[c2], a1 = sb[c2 + 1];
#pragma unroll
    for (int f = 0; f < FIN; f++) {
        float v = ip[f];
        a0 = fmaf(v, sw[f * 64 + c2], a0);
        a1 = fmaf(v, sw[f * 64 + c2 + 1], a1);
    }
    __nv_bfloat16 h0, l0, h1, l1;
    bsplit(a0, h0, l0);
    bsplit(a1, h1, l1);
    uint32_t hp = ((uint32_t)__bfloat16_as_ushort(h1) << 16) | (uint32_t)__bfloat16_as_ushort(h0);
    uint32_t lp = ((uint32_t)__bfloat16_as_ushort(l1) << 16) | (uint32_t)__bfloat16_as_ushort(l0);
    long oa = bt * 64 + c2;
    *reinterpret_cast<uint32_t*>(&xnh[oa]) = hp;
    *reinterpret_cast<uint32_t*>(&xnl[oa]) = lp;
}

// ---------------------------------------------------------------------------
// DFT (R14 config, unchanged): per CTA (s,b): D[128,64] += Fstack x {xh,xl};
// Fl x xl term dropped; bands interleaved across SMSPs.
#define DFT_STAGE_BYTES 32768
#define DFT_SMEM_BYTES (3 * DFT_STAGE_BYTES)
__global__ void __launch_bounds__(256) dft_mma(const __nv_bfloat16* __restrict__ xh,
                                               const __nv_bfloat16* __restrict__ xl) {
    extern __shared__ __align__(16) char sm[];
    int tid = threadIdx.x, lane = tid & 31, wid = tid >> 5;
    int warpm = wid >> 1, warpn = wid & 1;
    bool fullw = (warpm < 2);
    int s = blockIdx.x, b = blockIdx.y;
    float acc[2][4][4] = {};
    uint32_t smu = smem_u32(sm);
    const __nv_bfloat16* xhb = xh + (long)b * TT * 64;
    const __nv_bfloat16* xlb = xl + (long)b * TT * 64;

    auto issue = [&](int st, int it) {
        int tbase = s * KCHUNK + it * 64;
        uint32_t sA = smu + (uint32_t)st * DFT_STAGE_BYTES;
        uint32_t sBh = sA + 128 * 128;
        uint32_t sBl = sBh + 64 * 128;
#pragma unroll
        for (int j = 0; j < 4; j++) {
            int i = tid + j * 256;
            int r = i >> 3, c8 = i & 7;
            cpa16(sA + swz(r, c8), &g_Fbf[(long)r * TT + tbase + c8 * 8]);
        }
#pragma unroll
        for (int j = 0; j < 2; j++) {
            int i = tid + j * 256;
            int r = i >> 3, c8 = i & 7;
            long ga = (long)(tbase + r) * 64 + c8 * 8;
            cpa16(sBh + swz(r, c8), &xhb[ga]);
            cpa16(sBl + swz(r, c8), &xlb[ga]);
        }
    };

    issue(0, 0); CP_COMMIT();
    issue(1, 1); CP_COMMIT();

    int stage = 0;
    for (int it = 0; it < NITER; it++) {
        CP_WAIT(1);
        __syncthreads();
        int wstage = stage + 2 >= 3 ? stage - 1 : stage + 2;
        if (it + 2 < NITER) issue(wstage, it + 2);
        CP_COMMIT();

        uint32_t sA = smu + (uint32_t)stage * DFT_STAGE_BYTES;
        uint32_t sBh = sA + 128 * 128;
        uint32_t sBl = sBh + 64 * 128;
#pragma unroll
        for (int kk = 0; kk < 4; kk++) {
            uint32_t afr[2][4];
#pragma unroll
            for (int mt = 0; mt < 2; mt++) {
                int row = warpm * 32 + mt * 16 + (lane & 15);
                ldmA(afr[mt], sA + swz(row, kk * 2 + (lane >> 4)));
            }
#pragma unroll
            for (int ntp = 0; ntp < 2; ntp++) {
                int brow = kk * 16 + (lane & 15);
                int bchunk = warpn * 4 + ntp * 2 + (lane >> 4);
                uint32_t bh[4], bl[4];
                ldmB4(bh, sBh + swz(brow, bchunk));
                if (fullw) ldmB4(bl, sBl + swz(brow, bchunk));
#pragma unroll
                for (int mt = 0; mt < 2; mt++) {
                    mma16816(acc[mt][ntp * 2 + 0], afr[mt], bh + 0);
                    mma16816(acc[mt][ntp * 2 + 1], afr[mt], bh + 2);
                    if (fullw) {
                        mma16816(acc[mt][ntp * 2 + 0], afr[mt], bl + 0);
                        mma16816(acc[mt][ntp * 2 + 1], afr[mt], bl + 2);
                    }
                }
            }
        }
        stage = stage + 1 >= 3 ? 0 : stage + 1;
    }

    int g = lane >> 2, t4 = lane & 3;
    float* xp = g_Xp + ((long)s * BB + b) * 128 * 64;
#pragma unroll
    for (int mt = 0; mt < 2; mt++)
#pragma unroll
        for (int nt = 0; nt < 4; nt++) {
            int r = warpm * 32 + mt * 16 + g;
            int c = warpn * 32 + nt * 8 + t4 * 2;
            *reinterpret_cast<float2*>(&xp[(long)r * 64 + c]) =
                make_float2(acc[mt][nt][0], acc[mt][nt][1]);
            *reinterpret_cast<float2*>(&xp[(long)(r + 8) * 64 + c]) =
                make_float2(acc[mt][nt][2], acc[mt][nt][3]);
        }
}

// ---------------------------------------------------------------------------
// mix: 256 threads, 4 modes per block.
__global__ void __launch_bounds__(256) mix_k(const float* __restrict__ wr,
                                             const float* __restrict__ wi) {
    int kq = threadIdx.x >> 6;
    int k = blockIdx.x * 4 + kq;
    int b = blockIdx.y;
    int o = threadIdx.x & 63;
    __shared__ float sXr[4][64], sXi[4][64];
    float xr = 0.f, xi = 0.f;
#pragma unroll
    for (int s = 0; s < KSPLIT; s++) {
        const float* xp = g_Xp + ((long)s * BB + b) * 128 * 64;
        xr += xp[k * 64 + o] + xp[(64 + k) * 64 + o];
        xi += xp[(32 + k) * 64 + o] + xp[(96 + k) * 64 + o];
    }
    sXr[kq][o] = xr;
    sXi[kq][o] = xi;
    __syncthreads();
    float yr = 0.f, yi = 0.f;
    const float* wrk = wr + k * 64 * 64;
    const float* wik = wi + k * 64 * 64;
#pragma unroll 8
    for (int c = 0; c < 64; c++) {
        float wrv = wrk[c * 64 + o], wiv = wik[c * 64 + o];
        float cr = sXr[kq][c], ci = sXi[kq][c];
        yr = fmaf(cr, wrv, yr); yr = fmaf(-ci, wiv, yr);
        yi = fmaf(cr, wiv, yi); yi = fmaf(ci, wrv, yi);
    }
    const float inv = 1.0f / (float)TT;
    float zc, zs;
    if (k == 0) { zc = yr * inv; zs = 0.f; }
    else        { zc = yr * (2.0f * inv); zs = -yi * (2.0f * inv); }
    __nv_bfloat16 h, l;
    bsplit(zc, h, l);
    g_Zh[((long)b * 64 + k) * 64 + o] = h;
    g_Zl[((long)b * 64 + k) * 64 + o] = l;
    bsplit(zs, h, l);
    g_Zh[((long)b * 64 + 32 + k) * 64 + o] = h;
    g_Zl[((long)b * 64 + 32 + k) * 64 + o] = l;
}

// ---------------------------------------------------------------------------
// pw: streaming panel-pipelined fused irfft + conv + bias + GELU.
// Each CTA: 8 t-tiles of 128 rows; panels (Gh,Gl,Xh,Xl) flow through a
// 5-slot cp.async ring (4 in flight, 1 sync per panel); Z/C resident.
#define PW_TILES 8
#define PW_GROUPS (TT / 128 / PW_TILES)      // 8
#define PW_RING 5
#define PW_PANEL_BYTES 16384                 // 128 rows x 128B (swz)
#define PW_NP (PW_TILES * 4)                 // 32 panels
#define PW_SMEM_BYTES (PW_RING * PW_PANEL_BYTES + 4 * 8192)   // 112 KB
__global__ void __launch_bounds__(256) pw_mma(const __nv_bfloat16* __restrict__ xh_in,
                                              const __nv_bfloat16* __restrict__ xl_in,
                                              const __nv_bfloat16* __restrict__ Zh,
                                              const __nv_bfloat16* __restrict__ Zl,
                                              const __nv_bfloat16* __restrict__ Cwh,
                                              const __nv_bfloat16* __restrict__ Cwl,
                                              const float* __restrict__ convb,
                                              __nv_bfloat16* __restrict__ xh_out,
                                              __nv_bfloat16* __restrict__ xl_out) {
    extern __shared__ __align__(16) char smp[];
    uint32_t smu = smem_u32(smp);
    uint32_t ring = smu;
    uint32_t zc = smu + PW_RING * PW_PANEL_BYTES;   // sZh | sZl | sCh | sCl (8KB each)
    int tid = threadIdx.x, lane = tid & 31, wid = tid >> 5;
    int warpm = wid & 3, warpn = wid >> 2;
    int grp = blockIdx.x, b = blockIdx.y;
    int tbase0 = grp * PW_TILES * 128;

    // resident B tiles (group 0)
    {
        const __nv_bfloat16* zcsrc[4] = {Zh + (long)b * 4096, Zl + (long)b * 4096, Cwh, Cwl};
#pragma unroll
        for (int m = 0; m < 4; m++)
#pragma unroll
            for (int j = 0; j < 2; j++) {
                int i = tid + j * 256;
                int r = i >> 3, c8 = i & 7;
                cpa16(zc + (uint32_t)m * 8192 + swz(r, c8), &zcsrc[m][(long)r * 64 + c8 * 8]);
            }
        CP_COMMIT();
    }

    auto issue_panel = [&](int p) {
        int tile = p >> 2, which = p & 3;
        long toff = (long)(tbase0 + tile * 128) * 64;
        const __nv_bfloat16* src;
        if (which == 0)      src = g_Gh + toff;
        else if (which == 1) src = g_Gl + toff;
        else if (which == 2) src = xh_in + (long)b * TT * 64 + toff;
        else                 src = xl_in + (long)b * TT * 64 + toff;
        uint32_t slot = ring + (uint32_t)(p % PW_RING) * PW_PANEL_BYTES;
#pragma unroll
        for (int j = 0; j < 4; j++) {
            int i = tid + j * 256;
            int r = i >> 3, c8 = i & 7;
            cpa16(slot + swz(r, c8), src + (long)r * 64 + c8 * 8);
        }
        CP_COMMIT();
    };

    issue_panel(0); issue_panel(1); issue_panel(2); issue_panel(3);

    // B tile base per panel type (first pass / optional second pass)
    uint32_t B0[4] = {zc, zc, zc + 16384u, zc + 16384u};
    uint32_t B1[4] = {zc + 8192u, 0u, zc + 24576u, 0u};

    float acc[2][4][4] = {};
    for (int p = 0; p < PW_NP; p++) {
        CP_WAIT(3);
        __syncthreads();
        int which = p & 3;
        uint32_t slot = ring + (uint32_t)(p % PW_RING) * PW_PANEL_BYTES;
        uint32_t b0 = B0[which], b1 = B1[which];
#pragma unroll
        for (int kk = 0; kk < 4; kk++) {
            uint32_t afr[2][4];
#pragma unroll
            for (int mt = 0; mt < 2; mt++) {
                int row = warpm * 32 + mt * 16 + (lane & 15);
                ldmA(afr[mt], slot + swz(row, kk * 2 + (lane >> 4)));
            }
#pragma unroll
            for (int ntp = 0; ntp < 2; ntp++) {
                int brow = kk * 16 + (lane & 15);
                int bchunk = warpn * 4 + ntp * 2 + (lane >> 4);
                uint32_t bf0[4];
                ldmB4(bf0, b0 + swz(brow, bchunk));
#pragma unroll
                for (int mt = 0; mt < 2; mt++) {
                    mma16816(acc[mt][ntp * 2 + 0], afr[mt], bf0 + 0);
                    mma16816(acc[mt][ntp * 2 + 1], afr[mt], bf0 + 2);
                }
                if (b1) {
                    uint32_t bf1[4];
                    ldmB4(bf1, b1 + swz(brow, bchunk));
#pragma unroll
                    for (int mt = 0; mt < 2; mt++) {
                        mma16816(acc[mt][ntp * 2 + 0], afr[mt], bf1 + 0);
                        mma16816(acc[mt][ntp * 2 + 1], afr[mt], bf1 + 2);
                    }
                }
            }
        }
        if (p + 4 < PW_NP) issue_panel(p + 4); else CP_COMMIT();
        if (which == 3) {
            // epilogue for tile p>>2
            int t0 = tbase0 + (p >> 2) * 128;
            int g = lane >> 2, t4 = lane & 3;
#pragma unroll
            for (int mt = 0; mt < 2; mt++)
#pragma unroll
                for (int nt = 0; nt < 4; nt++) {
                    int r = warpm * 32 + mt * 16 + g;
                    int c = warpn * 32 + nt * 8 + t4 * 2;
                    float bc0 = convb[c], bc1 = convb[c + 1];
#pragma unroll
                    for (int half = 0; half < 2; half++) {
                        int rr = r + half * 8;
                        float v0 = gelu_exact(acc[mt][nt][half * 2 + 0] + bc0);
                        float v1 = gelu_exact(acc[mt][nt][half * 2 + 1] + bc1);
                        __nv_bfloat16 h0, l0, h1, l1;
                        bsplit(v0, h0, l0);
                        bsplit(v1, h1, l1);
                        uint32_t hp = ((uint32_t)__bfloat16_as_ushort(h1) << 16) |
                                      (uint32_t)__bfloat16_as_ushort(h0);
                        uint32_t lp = ((uint32_t)__bfloat16_as_ushort(l1) << 16) |
                                      (uint32_t)__bfloat16_as_ushort(l0);
                        long oa = ((long)b * TT + t0 + rr) * 64 + c;
                        *reinterpret_cast<uint32_t*>(&xh_out[oa]) = hp;
                        *reinterpret_cast<uint32_t*>(&xl_out[oa]) = lp;
                        acc[mt][nt][half * 2 + 0] = 0.f;
                        acc[mt][nt][half * 2 + 1] = 0.f;
                    }
                }
        }
    }
}

// ---------------------------------------------------------------------------
__global__ void final_k(const __nv_bfloat16* __restrict__ xnh,
                        const __nv_bfloat16* __restrict__ xnl,
                        const float* __restrict__ convw,
                        const float* __restrict__ convb,
                        const float* __restrict__ fc1w,
                        const float* __restrict__ fc1b,
                        const float* __restrict__ fc2w,
                        const float* __restrict__ fc2b,
                        float* __restrict__ out) {
    int b = blockIdx.x;
    int tid = threadIdx.x;
    __shared__ float x4[64];
    __shared__ float h[NFC1];
    __shared__ float grow[64], xrow[64];
    if (tid < 64) {
        int j = tid;
        grow[j] = __bfloat162float(g_Gh[(long)(TT - 1) * 64 + j]) +
                  __bfloat162float(g_Gl[(long)(TT - 1) * 64 + j]);
        long xa = ((long)b * TT + (TT - 1)) * 64 + j;
        xrow[j] = __bfloat162float(xnh[xa]) + __bfloat162float(xnl[xa]);
    }
    __syncthreads();
    if (tid < 64) {
        int c = tid;
        float pre = convb[c];
        const __nv_bfloat16* zh = g_Zh + (long)b * 4096;
        const __nv_bfloat16* zl = g_Zl + (long)b * 4096;
#pragma unroll 8
        for (int j = 0; j < 64; j++) {
            float z = __bfloat162float(zh[j * 64 + c]) + __bfloat162float(zl[j * 64 + c]);
            pre = fmaf(grow[j], z, pre);
            pre = fmaf(xrow[j], convw[j * 64 + c], pre);
        }
        x4[c] = gelu_exact(pre);
    }
    __syncthreads();
    {
        float acc = fc1b[tid];
#pragma unroll 8
        for (int c = 0; c < 64; c++) acc = fmaf(x4[c], fc1w[c * NFC1 + tid], acc);
        h[tid] = gelu_exact(acc);
    }
    __syncthreads();
    if (tid < NOUT) {
        float acc = fc2b[tid];
#pragma unroll 8
        for (int f = 0; f < NFC1; f++) acc = fmaf(h[f], fc2w[f * NOUT + tid], acc);
        out[b * NOUT + tid] = acc;
    }
}

// ---------------------------------------------------------------------------
extern "C" void kernel_launch(void* const* d_in, const int* in_sizes, int n_in,
                              void* d_out, int out_size) {
    const float* inputs = (const float*)d_in[0];
    const float* fc0_w  = (const float*)d_in[1];
    const float* fc0_b  = (const float*)d_in[2];
    const float* fwr    = (const float*)d_in[3];
    const float* fwi    = (const float*)d_in[4];
    const float* convw  = (const float*)d_in[5];
    const float* convb  = (const float*)d_in[6];
    const float* fc1w   = (const float*)d_in[7];
    const float* fc1b   = (const float*)d_in[8];
    const float* fc2w   = (const float*)d_in[9];
    const float* fc2b   = (const float*)d_in[10];
    float* out = (float*)d_out;

    cudaFuncSetAttribute(pw_mma, cudaFuncAttributeMaxDynamicSharedMemorySize, PW_SMEM_BYTES);
    cudaFuncSetAttribute(dft_mma, cudaFuncAttributeMaxDynamicSharedMemorySize, DFT_SMEM_BYTES);

    __nv_bfloat16 *xnh0, *xnl0, *zh, *zl, *cwh, *cwl;
    cudaGetSymbolAddress((void**)&xnh0, g_xnh);
    cudaGetSymbolAddress((void**)&xnl0, g_xnl);
    cudaGetSymbolAddress((void**)&zh, g_Zh);
    cudaGetSymbolAddress((void**)&zl, g_Zl);
    cudaGetSymbolAddress((void**)&cwh, g_cwh);
    cudaGetSymbolAddress((void**)&cwl, g_cwl);
    __nv_bfloat16* xnh1 = xnh0 + XELEMS;
    __nv_bfloat16* xnl1 = xnl0 + XELEMS;

    twiddle_k<<<(MODES * TT + 255) / 256, 256>>>();
    cwprep<<<(NLAYERS * 64 * 64 + 255) / 256, 256>>>(convw);
    fc0_bf<<<(int)(((long)BB * TT * 32) / 256), 256>>>(inputs, fc0_w, fc0_b, xnh0, xnl0);

    __nv_bfloat16 *cnh = xnh0, *cnl = xnl0, *nnh = xnh1, *nnl = xnl1;
    for (int l = 0; l < NLAYERS; l++) {
        dft_mma<<<dim3(KSPLIT, BB), 256, DFT_SMEM_BYTES>>>(cnh, cnl);
        mix_k<<<dim3(MODES / 4, BB), 256>>>(fwr + (long)l * MODES * 64 * 64,
                                            fwi + (long)l * MODES * 64 * 64);
        if (l < NLAYERS - 1) {
            pw_mma<<<dim3(PW_GROUPS, BB), 256, PW_SMEM_BYTES>>>(
                cnh, cnl, zh, zl, cwh + (long)l * 4096, cwl + (long)l * 4096,
                convb + (long)l * 64, nnh, nnl);
            __nv_bfloat16* t;
            t = cnh; cnh = nnh; nnh = t;
            t = cnl; cnl = nnl; nnl = t;
        } else {
            final_k<<<BB, 128>>>(cnh, cnl, convw + (long)l * 4096, convb + (long)l * 64,
                                 fc1w, fc1b, fc2w, fc2b, out);
        }
    }
}

// round 16
// speedup vs baseline: 1.1233x; 1.1233x over previous
#include <cuda_runtime.h>
#include <cuda_bf16.h>
#include <stdint.h>
#include <math.h>

#define BB 64
#define TT 8192
#define FIN 6
#define MODES 32
#define NLAYERS 4
#define NFC1 128
#define NOUT 7
#define KSPLIT 4
#define KCHUNK (TT / KSPLIT)      // 2048
#define NITER (KCHUNK / 64)       // 32
#define XELEMS (BB * TT * 64)
#define DPAD 72                   // smem row pad (elems) used by pw kernel

// ---------------- device globals ----------------
__device__ __nv_bfloat16 g_Fbf[128 * TT];   // rows 0-31 cos_hi, 32-63 (-sin)_hi, 64-95 cos_lo, 96-127 (-sin)_lo
__device__ __nv_bfloat16 g_Gh[TT * 64];     // irfft basis [t][j] hi
__device__ __nv_bfloat16 g_Gl[TT * 64];
__device__ __nv_bfloat16 g_xnh[2][XELEMS];  // x [b][t][c] hi, double buffered
__device__ __nv_bfloat16 g_xnl[2][XELEMS];
__device__ float g_Xp[KSPLIT * BB * 128 * 64];
__device__ __nv_bfloat16 g_Zh[BB * 64 * 64];
__device__ __nv_bfloat16 g_Zl[BB * 64 * 64];
__device__ __nv_bfloat16 g_cwh[NLAYERS * 64 * 64];
__device__ __nv_bfloat16 g_cwl[NLAYERS * 64 * 64];

// ---------------- helpers ----------------
__device__ __forceinline__ float gelu_exact(float v) {
    return 0.5f * v * (1.0f + erff(v * 0.70710678118654752440f));
}
__device__ __forceinline__ void bsplit(float v, __nv_bfloat16& h, __nv_bfloat16& l) {
    h = __float2bfloat16(v);
    l = __float2bfloat16(v - __bfloat162float(h));
}
__device__ __forceinline__ uint32_t smem_u32(const void* p) {
    uint32_t a;
    asm("{ .reg .u64 t; cvta.to.shared.u64 t, %1; cvt.u32.u64 %0, t; }" : "=r"(a) : "l"(p));
    return a;
}
__device__ __forceinline__ void cpa16(uint32_t s, const void* g) {
    asm volatile("cp.async.cg.shared.global [%0], [%1], 16;" :: "r"(s), "l"(g));
}
#define CP_COMMIT() asm volatile("cp.async.commit_group;" ::: "memory")
#define CP_WAIT(n)  asm volatile("cp.async.wait_group %0;" :: "n"(n) : "memory")

__device__ __forceinline__ void ldmA(uint32_t* a, uint32_t addr) {
    asm volatile("ldmatrix.sync.aligned.m8n8.x4.shared.b16 {%0,%1,%2,%3}, [%4];"
                 : "=r"(a[0]), "=r"(a[1]), "=r"(a[2]), "=r"(a[3]) : "r"(addr));
}
__device__ __forceinline__ void ldmB4(uint32_t* b, uint32_t addr) {
    asm volatile("ldmatrix.sync.aligned.m8n8.x4.trans.shared.b16 {%0,%1,%2,%3}, [%4];"
                 : "=r"(b[0]), "=r"(b[1]), "=r"(b[2]), "=r"(b[3]) : "r"(addr));
}
__device__ __forceinline__ void mma16816(float* d, const uint32_t* a, const uint32_t* b) {
    asm volatile(
        "mma.sync.aligned.m16n8k16.row.col.f32.bf16.bf16.f32 "
        "{%0,%1,%2,%3}, {%4,%5,%6,%7}, {%8,%9}, {%0,%1,%2,%3};"
        : "+f"(d[0]), "+f"(d[1]), "+f"(d[2]), "+f"(d[3])
        : "r"(a[0]), "r"(a[1]), "r"(a[2]), "r"(a[3]), "r"(b[0]), "r"(b[1]));
}
// swizzled byte offset within a tile of 128B rows: chunk index ^= (row & 7)
__device__ __forceinline__ uint32_t swz(int row, int chunk) {
    return (uint32_t)(row * 128 + ((chunk ^ (row & 7)) << 4));
}

// ---------------------------------------------------------------------------
__global__ void twiddle_k() {
    int idx = blockIdx.x * blockDim.x + threadIdx.x;
    if (idx >= MODES * TT) return;
    int k = idx >> 13;
    int t = idx & (TT - 1);
    int m = (k * t) & (TT - 1);
    float ang = 2.0f * (float)m / (float)TT;
    float s, c;
    sincospif(ang, &s, &c);
    __nv_bfloat16 h, l;
    bsplit(c, h, l);
    g_Fbf[k * TT + t] = h;  g_Fbf[(64 + k) * TT + t] = l;
    g_Gh[t * 64 + k] = h;   g_Gl[t * 64 + k] = l;
    bsplit(-s, h, l);
    g_Fbf[(32 + k) * TT + t] = h;  g_Fbf[(96 + k) * TT + t] = l;
    bsplit(s, h, l);
    g_Gh[t * 64 + 32 + k] = h;  g_Gl[t * 64 + 32 + k] = l;
}

__global__ void cwprep(const float* __restrict__ convw) {
    int idx = blockIdx.x * blockDim.x + threadIdx.x;
    if (idx >= NLAYERS * 64 * 64) return;
    __nv_bfloat16 h, l;
    bsplit(convw[idx], h, l);
    g_cwh[idx] = h;
    g_cwl[idx] = l;
}

// ---------------------------------------------------------------------------
// fc0: 2 channels per thread, packed 32-bit stores
__global__ void __launch_bounds__(256) fc0_bf(const float* __restrict__ inp,
                                              const float* __restrict__ w,
                                              const float* __restrict__ bias,
                                              __nv_bfloat16* __restrict__ xnh,
                                              __nv_bfloat16* __restrict__ xnl) {
    __shared__ float sw[FIN * 64];
    __shared__ float sb[64];
    int tid = threadIdx.x;
    for (int i = tid; i < FIN * 64; i += 256) sw[i] = w[i];
    if (tid < 64) sb[tid] = bias[tid];
    __syncthreads();
    long gid = (long)blockIdx.x * 256 + tid;         // over B*T*32
    int c2 = (int)(gid & 31) * 2;
    long bt = gid >> 5;
    const float* ip = inp + bt * FIN;
    float a0 = sb[c2], a1 = sb[c2 + 1];
#pragma unroll
    for (int f = 0; f < FIN; f++) {
        float v = ip[f];
        a0 = fmaf(v, sw[f * 64 + c2], a0);
        a1 = fmaf(v, sw[f * 64 + c2 + 1], a1);
    }
    __nv_bfloat16 h0, l0, h1, l1;
    bsplit(a0, h0, l0);
    bsplit(a1, h1, l1);
    uint32_t hp = ((uint32_t)__bfloat16_as_ushort(h1) << 16) | (uint32_t)__bfloat16_as_ushort(h0);
    uint32_t lp = ((uint32_t)__bfloat16_as_ushort(l1) << 16) | (uint32_t)__bfloat16_as_ushort(l0);
    long oa = bt * 64 + c2;
    *reinterpret_cast<uint32_t*>(&xnh[oa]) = hp;
    *reinterpret_cast<uint32_t*>(&xnl[oa]) = lp;
}

// ---------------------------------------------------------------------------
// DFT (R14 config, unchanged): per CTA (s,b): D[128,64] += Fstack x {xh,xl};
// Fl x xl term dropped; bands interleaved across SMSPs.
#define DFT_STAGE_BYTES 32768
#define DFT_SMEM_BYTES (3 * DFT_STAGE_BYTES)
__global__ void __launch_bounds__(256) dft_mma(const __nv_bfloat16* __restrict__ xh,
                                               const __nv_bfloat16* __restrict__ xl) {
    extern __shared__ __align__(16) char sm[];
    int tid = threadIdx.x, lane = tid & 31, wid = tid >> 5;
    int warpm = wid >> 1, warpn = wid & 1;
    bool fullw = (warpm < 2);
    int s = blockIdx.x, b = blockIdx.y;
    float acc[2][4][4] = {};
    uint32_t smu = smem_u32(sm);
    const __nv_bfloat16* xhb = xh + (long)b * TT * 64;
    const __nv_bfloat16* xlb = xl + (long)b * TT * 64;

    auto issue = [&](int st, int it) {
        int tbase = s * KCHUNK + it * 64;
        uint32_t sA = smu + (uint32_t)st * DFT_STAGE_BYTES;
        uint32_t sBh = sA + 128 * 128;
        uint32_t sBl = sBh + 64 * 128;
#pragma unroll
        for (int j = 0; j < 4; j++) {
            int i = tid + j * 256;
            int r = i >> 3, c8 = i & 7;
            cpa16(sA + swz(r, c8), &g_Fbf[(long)r * TT + tbase + c8 * 8]);
        }
#pragma unroll
        for (int j = 0; j < 2; j++) {
            int i = tid + j * 256;
            int r = i >> 3, c8 = i & 7;
            long ga = (long)(tbase + r) * 64 + c8 * 8;
            cpa16(sBh + swz(r, c8), &xhb[ga]);
            cpa16(sBl + swz(r, c8), &xlb[ga]);
        }
    };

    issue(0, 0); CP_COMMIT();
    issue(1, 1); CP_COMMIT();

    int stage = 0;
    for (int it = 0; it < NITER; it++) {
        CP_WAIT(1);
        __syncthreads();
        int wstage = stage + 2 >= 3 ? stage - 1 : stage + 2;
        if (it + 2 < NITER) issue(wstage, it + 2);
        CP_COMMIT();

        uint32_t sA = smu + (uint32_t)stage * DFT_STAGE_BYTES;
        uint32_t sBh = sA + 128 * 128;
        uint32_t sBl = sBh + 64 * 128;
#pragma unroll
        for (int kk = 0; kk < 4; kk++) {
            uint32_t afr[2][4];
#pragma unroll
            for (int mt = 0; mt < 2; mt++) {
                int row = warpm * 32 + mt * 16 + (lane & 15);
                ldmA(afr[mt], sA + swz(row, kk * 2 + (lane >> 4)));
            }
#pragma unroll
            for (int ntp = 0; ntp < 2; ntp++) {
                int brow = kk * 16 + (lane & 15);
                int bchunk = warpn * 4 + ntp * 2 + (lane >> 4);
                uint32_t bh[4], bl[4];
                ldmB4(bh, sBh + swz(brow, bchunk));
                if (fullw) ldmB4(bl, sBl + swz(brow, bchunk));
#pragma unroll
                for (int mt = 0; mt < 2; mt++) {
                    mma16816(acc[mt][ntp * 2 + 0], afr[mt], bh + 0);
                    mma16816(acc[mt][ntp * 2 + 1], afr[mt], bh + 2);
                    if (fullw) {
                        mma16816(acc[mt][ntp * 2 + 0], afr[mt], bl + 0);
                        mma16816(acc[mt][ntp * 2 + 1], afr[mt], bl + 2);
                    }
                }
            }
        }
        stage = stage + 1 >= 3 ? 0 : stage + 1;
    }

    int g = lane >> 2, t4 = lane & 3;
    float* xp = g_Xp + ((long)s * BB + b) * 128 * 64;
#pragma unroll
    for (int mt = 0; mt < 2; mt++)
#pragma unroll
        for (int nt = 0; nt < 4; nt++) {
            int r = warpm * 32 + mt * 16 + g;
            int c = warpn * 32 + nt * 8 + t4 * 2;
            *reinterpret_cast<float2*>(&xp[(long)r * 64 + c]) =
                make_float2(acc[mt][nt][0], acc[mt][nt][1]);
            *reinterpret_cast<float2*>(&xp[(long)(r + 8) * 64 + c]) =
                make_float2(acc[mt][nt][2], acc[mt][nt][3]);
        }
}

// ---------------------------------------------------------------------------
// mix: 256 threads, 4 modes per block.
__global__ void __launch_bounds__(256) mix_k(const float* __restrict__ wr,
                                             const float* __restrict__ wi) {
    int kq = threadIdx.x >> 6;
    int k = blockIdx.x * 4 + kq;
    int b = blockIdx.y;
    int o = threadIdx.x & 63;
    __shared__ float sXr[4][64], sXi[4][64];
    float xr = 0.f, xi = 0.f;
#pragma unroll
    for (int s = 0; s < KSPLIT; s++) {
        const float* xp = g_Xp + ((long)s * BB + b) * 128 * 64;
        xr += xp[k * 64 + o] + xp[(64 + k) * 64 + o];
        xi += xp[(32 + k) * 64 + o] + xp[(96 + k) * 64 + o];
    }
    sXr[kq][o] = xr;
    sXi[kq][o] = xi;
    __syncthreads();
    float yr = 0.f, yi = 0.f;
    const float* wrk = wr + k * 64 * 64;
    const float* wik = wi + k * 64 * 64;
#pragma unroll 8
    for (int c = 0; c < 64; c++) {
        float wrv = wrk[c * 64 + o], wiv = wik[c * 64 + o];
        float cr = sXr[kq][c], ci = sXi[kq][c];
        yr = fmaf(cr, wrv, yr); yr = fmaf(-ci, wiv, yr);
        yi = fmaf(cr, wiv, yi); yi = fmaf(ci, wrv, yi);
    }
    const float inv = 1.0f / (float)TT;
    float zc, zs;
    if (k == 0) { zc = yr * inv; zs = 0.f; }
    else        { zc = yr * (2.0f * inv); zs = -yi * (2.0f * inv); }
    __nv_bfloat16 h, l;
    bsplit(zc, h, l);
    g_Zh[((long)b * 64 + k) * 64 + o] = h;
    g_Zl[((long)b * 64 + k) * 64 + o] = l;
    bsplit(zs, h, l);
    g_Zh[((long)b * 64 + 32 + k) * 64 + o] = h;
    g_Zl[((long)b * 64 + 32 + k) * 64 + o] = l;
}

// ---------------------------------------------------------------------------
// pw: fused irfft + conv + bias + GELU. R14 structure, but loads split into
// 4 commit groups ordered by consumption with progressive cp.async waits:
// group0 {Gh + Z/C tiles}, group1 {Gl}, group2 {Xh}, group3 {Xl}.
// Compute of ai-group g overlaps the in-flight loads of groups g+1..3.
#define PW_SMEM_BYTES ((4 * 128 * DPAD + 4 * 64 * DPAD) * 2)
__global__ void __launch_bounds__(256) pw_mma(const __nv_bfloat16* __restrict__ xh_in,
                                              const __nv_bfloat16* __restrict__ xl_in,
                                              const __nv_bfloat16* __restrict__ Zh,
                                              const __nv_bfloat16* __restrict__ Zl,
                                              const __nv_bfloat16* __restrict__ Cwh,
                                              const __nv_bfloat16* __restrict__ Cwl,
                                              const float* __restrict__ convb,
                                              __nv_bfloat16* __restrict__ xh_out,
                                              __nv_bfloat16* __restrict__ xl_out) {
    extern __shared__ __align__(16) __nv_bfloat16 smp[];
    __nv_bfloat16* sGh = smp;
    __nv_bfloat16* sGl = smp + 128 * DPAD;
    __nv_bfloat16* sXh = smp + 2 * 128 * DPAD;
    __nv_bfloat16* sXl = smp + 3 * 128 * DPAD;
    __nv_bfloat16* sZh = smp + 4 * 128 * DPAD;
    __nv_bfloat16* sZl = sZh + 64 * DPAD;
    __nv_bfloat16* sCh = sZh + 2 * 64 * DPAD;
    __nv_bfloat16* sCl = sZh + 3 * 64 * DPAD;
    int tid = threadIdx.x, lane = tid & 31, wid = tid >> 5;
    int warpm = wid & 3, warpn = wid >> 2;
    int t0 = blockIdx.x * 128, b = blockIdx.y;

    const __nv_bfloat16* aGh = g_Gh + (long)t0 * 64;
    const __nv_bfloat16* aGl = g_Gl + (long)t0 * 64;
    const __nv_bfloat16* aXh = xh_in + ((long)b * TT + t0) * 64;
    const __nv_bfloat16* aXl = xl_in + ((long)b * TT + t0) * 64;

    // commit group 0: Gh panel + all four B tiles (needed by ai=0)
    {
#pragma unroll
        for (int j = 0; j < 4; j++) {
            int i = tid + j * 256;
            int r = i >> 3, c8 = (i & 7) * 8;
            cpa16(smem_u32(sGh) + (uint32_t)(r * DPAD + c8) * 2, &aGh[(long)r * 64 + c8]);
        }
        const __nv_bfloat16* bZh = Zh + (long)b * 4096;
        const __nv_bfloat16* bZl = Zl + (long)b * 4096;
#pragma unroll
        for (int j = 0; j < 2; j++) {
            int i = tid + j * 256;
            int r = i >> 3, c8 = (i & 7) * 8;
            uint32_t so = smem_u32(sZh) + (uint32_t)(r * DPAD + c8) * 2;
            long go = (long)r * 64 + c8;
            cpa16(so, &bZh[go]);
            cpa16(so + 64 * DPAD * 2, &bZl[go]);
            cpa16(so + 2 * 64 * DPAD * 2, &Cwh[go]);
            cpa16(so + 3 * 64 * DPAD * 2, &Cwl[go]);
        }
        CP_COMMIT();
    }
    // commit groups 1..3: Gl, Xh, Xl panels
    {
#pragma unroll
        for (int j = 0; j < 4; j++) {
            int i = tid + j * 256;
            int r = i >> 3, c8 = (i & 7) * 8;
            cpa16(smem_u32(sGl) + (uint32_t)(r * DPAD + c8) * 2, &aGl[(long)r * 64 + c8]);
        }
        CP_COMMIT();
#pragma unroll
        for (int j = 0; j < 4; j++) {
            int i = tid + j * 256;
            int r = i >> 3, c8 = (i & 7) * 8;
            cpa16(smem_u32(sXh) + (uint32_t)(r * DPAD + c8) * 2, &aXh[(long)r * 64 + c8]);
        }
        CP_COMMIT();
#pragma unroll
        for (int j = 0; j < 4; j++) {
            int i = tid + j * 256;
            int r = i >> 3, c8 = (i & 7) * 8;
            cpa16(smem_u32(sXl) + (uint32_t)(r * DPAD + c8) * 2, &aXl[(long)r * 64 + c8]);
        }
        CP_COMMIT();
    }

    float acc[2][4][4] = {};
    // one ai-group of MMAs: A panel x (B0 [, B1])
    auto compute_group = [&](uint32_t Au, uint32_t B0, uint32_t B1) {
#pragma unroll
        for (int kk = 0; kk < 4; kk++) {
            uint32_t afr[2][4];
#pragma unroll
            for (int mt = 0; mt < 2; mt++)
                ldmA(afr[mt], Au + (uint32_t)((warpm * 32 + mt * 16 + (lane & 15)) * DPAD
                                              + kk * 16 + (lane >> 4) * 8) * 2);
#pragma unroll
            for (int ntp = 0; ntp < 2; ntp++) {
                uint32_t boff = (uint32_t)((kk * 16 + (lane & 15)) * DPAD
                                           + warpn * 32 + ntp * 16 + (lane >> 4) * 8) * 2;
                uint32_t bf0[4];
                ldmB4(bf0, B0 + boff);
#pragma unroll
                for (int mt = 0; mt < 2; mt++) {
                    mma16816(acc[mt][ntp * 2 + 0], afr[mt], bf0 + 0);
                    mma16816(acc[mt][ntp * 2 + 1], afr[mt], bf0 + 2);
                }
                if (B1) {
                    uint32_t bf1[4];
                    ldmB4(bf1, B1 + boff);
#pragma unroll
                    for (int mt = 0; mt < 2; mt++) {
                        mma16816(acc[mt][ntp * 2 + 0], afr[mt], bf1 + 0);
                        mma16816(acc[mt][ntp * 2 + 1], afr[mt], bf1 + 2);
                    }
                }
            }
        }
    };

    CP_WAIT(3); __syncthreads();
    compute_group(smem_u32(sGh), smem_u32(sZh), smem_u32(sZl));
    CP_WAIT(2); __syncthreads();
    compute_group(smem_u32(sGl), smem_u32(sZh), 0u);
    CP_WAIT(1); __syncthreads();
    compute_group(smem_u32(sXh), smem_u32(sCh), smem_u32(sCl));
    CP_WAIT(0); __syncthreads();
    compute_group(smem_u32(sXl), smem_u32(sCh), 0u);

    int g = lane >> 2, t4 = lane & 3;
#pragma unroll
    for (int mt = 0; mt < 2; mt++)
#pragma unroll
        for (int nt = 0; nt < 4; nt++) {
            int r = warpm * 32 + mt * 16 + g;
            int c = warpn * 32 + nt * 8 + t4 * 2;
            float bc0 = convb[c], bc1 = convb[c + 1];
#pragma unroll
            for (int half = 0; half < 2; half++) {
                int rr = r + half * 8;
                float v0 = gelu_exact(acc[mt][nt][half * 2 + 0] + bc0);
                float v1 = gelu_exact(acc[mt][nt][half * 2 + 1] + bc1);
                __nv_bfloat16 h0, l0, h1, l1;
                bsplit(v0, h0, l0);
                bsplit(v1, h1, l1);
                uint32_t hp = ((uint32_t)__bfloat16_as_ushort(h1) << 16) |
                              (uint32_t)__bfloat16_as_ushort(h0);
                uint32_t lp = ((uint32_t)__bfloat16_as_ushort(l1) << 16) |
                              (uint32_t)__bfloat16_as_ushort(l0);
                long oa = ((long)b * TT + t0 + rr) * 64 + c;
                *reinterpret_cast<uint32_t*>(&xh_out[oa]) = hp;
                *reinterpret_cast<uint32_t*>(&xl_out[oa]) = lp;
            }
        }
}

// ---------------------------------------------------------------------------
__global__ void final_k(const __nv_bfloat16* __restrict__ xnh,
                        const __nv_bfloat16* __restrict__ xnl,
                        const float* __restrict__ convw,
                        const float* __restrict__ convb,
                        const float* __restrict__ fc1w,
                        const float* __restrict__ fc1b,
                        const float* __restrict__ fc2w,
                        const float* __restrict__ fc2b,
                        float* __restrict__ out) {
    int b = blockIdx.x;
    int tid = threadIdx.x;
    __shared__ float x4[64];
    __shared__ float h[NFC1];
    __shared__ float grow[64], xrow[64];
    if (tid < 64) {
        int j = tid;
        grow[j] = __bfloat162float(g_Gh[(long)(TT - 1) * 64 + j]) +
                  __bfloat162float(g_Gl[(long)(TT - 1) * 64 + j]);
        long xa = ((long)b * TT + (TT - 1)) * 64 + j;
        xrow[j] = __bfloat162float(xnh[xa]) + __bfloat162float(xnl[xa]);
    }
    __syncthreads();
    if (tid < 64) {
        int c = tid;
        float pre = convb[c];
        const __nv_bfloat16* zh = g_Zh + (long)b * 4096;
        const __nv_bfloat16* zl = g_Zl + (long)b * 4096;
#pragma unroll 8
        for (int j = 0; j < 64; j++) {
            float z = __bfloat162float(zh[j * 64 + c]) + __bfloat162float(zl[j * 64 + c]);
            pre = fmaf(grow[j], z, pre);
            pre = fmaf(xrow[j], convw[j * 64 + c], pre);
        }
        x4[c] = gelu_exact(pre);
    }
    __syncthreads();
    {
        float acc = fc1b[tid];
#pragma unroll 8
        for (int c = 0; c < 64; c++) acc = fmaf(x4[c], fc1w[c * NFC1 + tid], acc);
        h[tid] = gelu_exact(acc);
    }
    __syncthreads();
    if (tid < NOUT) {
        float acc = fc2b[tid];
#pragma unroll 8
        for (int f = 0; f < NFC1; f++) acc = fmaf(h[f], fc2w[f * NOUT + tid], acc);
        out[b * NOUT + tid] = acc;
    }
}

// ---------------------------------------------------------------------------
extern "C" void kernel_launch(void* const* d_in, const int* in_sizes, int n_in,
                              void* d_out, int out_size) {
    const float* inputs = (const float*)d_in[0];
    const float* fc0_w  = (const float*)d_in[1];
    const float* fc0_b  = (const float*)d_in[2];
    const float* fwr    = (const float*)d_in[3];
    const float* fwi    = (const float*)d_in[4];
    const float* convw  = (const float*)d_in[5];
    const float* convb  = (const float*)d_in[6];
    const float* fc1w   = (const float*)d_in[7];
    const float* fc1b   = (const float*)d_in[8];
    const float* fc2w   = (const float*)d_in[9];
    const float* fc2b   = (const float*)d_in[10];
    float* out = (float*)d_out;

    cudaFuncSetAttribute(pw_mma, cudaFuncAttributeMaxDynamicSharedMemorySize, PW_SMEM_BYTES);
    cudaFuncSetAttribute(dft_mma, cudaFuncAttributeMaxDynamicSharedMemorySize, DFT_SMEM_BYTES);

    __nv_bfloat16 *xnh0, *xnl0, *zh, *zl, *cwh, *cwl;
    cudaGetSymbolAddress((void**)&xnh0, g_xnh);
    cudaGetSymbolAddress((void**)&xnl0, g_xnl);
    cudaGetSymbolAddress((void**)&zh, g_Zh);
    cudaGetSymbolAddress((void**)&zl, g_Zl);
    cudaGetSymbolAddress((void**)&cwh, g_cwh);
    cudaGetSymbolAddress((void**)&cwl, g_cwl);
    __nv_bfloat16* xnh1 = xnh0 + XELEMS;
    __nv_bfloat16* xnl1 = xnl0 + XELEMS;

    twiddle_k<<<(MODES * TT + 255) / 256, 256>>>();
    cwprep<<<(NLAYERS * 64 * 64 + 255) / 256, 256>>>(convw);
    fc0_bf<<<(int)(((long)BB * TT * 32) / 256), 256>>>(inputs, fc0_w, fc0_b, xnh0, xnl0);

    __nv_bfloat16 *cnh = xnh0, *cnl = xnl0, *nnh = xnh1, *nnl = xnl1;
    for (int l = 0; l < NLAYERS; l++) {
        dft_mma<<<dim3(KSPLIT, BB), 256, DFT_SMEM_BYTES>>>(cnh, cnl);
        mix_k<<<dim3(MODES / 4, BB), 256>>>(fwr + (long)l * MODES * 64 * 64,
                                            fwi + (long)l * MODES * 64 * 64);
        if (l < NLAYERS - 1) {
            pw_mma<<<dim3(TT / 128, BB), 256, PW_SMEM_BYTES>>>(
                cnh, cnl, zh, zl, cwh + (long)l * 4096, cwl + (long)l * 4096,
                convb + (long)l * 64, nnh, nnl);
            __nv_bfloat16* t;
            t = cnh; cnh = nnh; nnh = t;
            t = cnl; cnl = nnl; nnl = t;
        } else {
            final_k<<<BB, 128>>>(cnh, cnl, convw + (long)l * 4096, convb + (long)l * 64,
                                 fc1w, fc1b, fc2w, fc2b, out);
        }
    }
}

// round 17
// speedup vs baseline: 1.1367x; 1.0120x over previous
#include <cuda_runtime.h>
#include <cuda_bf16.h>
#include <stdint.h>
#include <math.h>

#define BB 64
#define TT 8192
#define FIN 6
#define MODES 32
#define NLAYERS 4
#define NFC1 128
#define NOUT 7
#define KSPLIT 8
#define KCHUNK (TT / KSPLIT)      // 1024
#define NITER (KCHUNK / 64)       // 16
#define XELEMS (BB * TT * 64)
#define DPAD 72                   // smem row pad (elems) used by pw kernel

// ---------------- device globals ----------------
__device__ __nv_bfloat16 g_Fbf[128 * TT];   // rows 0-31 cos_hi, 32-63 (-sin)_hi, 64-95 cos_lo, 96-127 (-sin)_lo
__device__ __nv_bfloat16 g_Gh[TT * 64];     // irfft basis [t][j] hi
__device__ __nv_bfloat16 g_Gl[TT * 64];
__device__ __nv_bfloat16 g_xnh[2][XELEMS];  // x [b][t][c] hi, double buffered
__device__ __nv_bfloat16 g_xnl[2][XELEMS];
__device__ float g_Xp[KSPLIT * BB * 128 * 64];
__device__ __nv_bfloat16 g_Zh[BB * 64 * 64];
__device__ __nv_bfloat16 g_Zl[BB * 64 * 64];
__device__ __nv_bfloat16 g_cwh[NLAYERS * 64 * 64];
__device__ __nv_bfloat16 g_cwl[NLAYERS * 64 * 64];

// ---------------- helpers ----------------
__device__ __forceinline__ float gelu_exact(float v) {
    return 0.5f * v * (1.0f + erff(v * 0.70710678118654752440f));
}
__device__ __forceinline__ void bsplit(float v, __nv_bfloat16& h, __nv_bfloat16& l) {
    h = __float2bfloat16(v);
    l = __float2bfloat16(v - __bfloat162float(h));
}
__device__ __forceinline__ uint32_t smem_u32(const void* p) {
    uint32_t a;
    asm("{ .reg .u64 t; cvta.to.shared.u64 t, %1; cvt.u32.u64 %0, t; }" : "=r"(a) : "l"(p));
    return a;
}
__device__ __forceinline__ void cpa16(uint32_t s, const void* g) {
    asm volatile("cp.async.cg.shared.global [%0], [%1], 16;" :: "r"(s), "l"(g));
}
#define CP_COMMIT() asm volatile("cp.async.commit_group;" ::: "memory")
#define CP_WAIT(n)  asm volatile("cp.async.wait_group %0;" :: "n"(n) : "memory")

__device__ __forceinline__ void ldmA(uint32_t* a, uint32_t addr) {
    asm volatile("ldmatrix.sync.aligned.m8n8.x4.shared.b16 {%0,%1,%2,%3}, [%4];"
                 : "=r"(a[0]), "=r"(a[1]), "=r"(a[2]), "=r"(a[3]) : "r"(addr));
}
__device__ __forceinline__ void ldmB4(uint32_t* b, uint32_t addr) {
    asm volatile("ldmatrix.sync.aligned.m8n8.x4.trans.shared.b16 {%0,%1,%2,%3}, [%4];"
                 : "=r"(b[0]), "=r"(b[1]), "=r"(b[2]), "=r"(b[3]) : "r"(addr));
}
__device__ __forceinline__ void mma16816(float* d, const uint32_t* a, const uint32_t* b) {
    asm volatile(
        "mma.sync.aligned.m16n8k16.row.col.f32.bf16.bf16.f32 "
        "{%0,%1,%2,%3}, {%4,%5,%6,%7}, {%8,%9}, {%0,%1,%2,%3};"
        : "+f"(d[0]), "+f"(d[1]), "+f"(d[2]), "+f"(d[3])
        : "r"(a[0]), "r"(a[1]), "r"(a[2]), "r"(a[3]), "r"(b[0]), "r"(b[1]));
}
// swizzled byte offset within a tile of 128B rows: chunk index ^= (row & 7)
__device__ __forceinline__ uint32_t swz(int row, int chunk) {
    return (uint32_t)(row * 128 + ((chunk ^ (row & 7)) << 4));
}

// ---------------------------------------------------------------------------
__global__ void twiddle_k() {
    int idx = blockIdx.x * blockDim.x + threadIdx.x;
    if (idx >= MODES * TT) return;
    int k = idx >> 13;
    int t = idx & (TT - 1);
    int m = (k * t) & (TT - 1);
    float ang = 2.0f * (float)m / (float)TT;
    float s, c;
    sincospif(ang, &s, &c);
    __nv_bfloat16 h, l;
    bsplit(c, h, l);
    g_Fbf[k * TT + t] = h;  g_Fbf[(64 + k) * TT + t] = l;
    g_Gh[t * 64 + k] = h;   g_Gl[t * 64 + k] = l;
    bsplit(-s, h, l);
    g_Fbf[(32 + k) * TT + t] = h;  g_Fbf[(96 + k) * TT + t] = l;
    bsplit(s, h, l);
    g_Gh[t * 64 + 32 + k] = h;  g_Gl[t * 64 + 32 + k] = l;
}

__global__ void cwprep(const float* __restrict__ convw) {
    int idx = blockIdx.x * blockDim.x + threadIdx.x;
    if (idx >= NLAYERS * 64 * 64) return;
    __nv_bfloat16 h, l;
    bsplit(convw[idx], h, l);
    g_cwh[idx] = h;
    g_cwl[idx] = l;
}

// ---------------------------------------------------------------------------
// fc0: 2 channels per thread, packed 32-bit stores
__global__ void __launch_bounds__(256) fc0_bf(const float* __restrict__ inp,
                                              const float* __restrict__ w,
                                              const float* __restrict__ bias,
                                              __nv_bfloat16* __restrict__ xnh,
                                              __nv_bfloat16* __restrict__ xnl) {
    __shared__ float sw[FIN * 64];
    __shared__ float sb[64];
    int tid = threadIdx.x;
    for (int i = tid; i < FIN * 64; i += 256) sw[i] = w[i];
    if (tid < 64) sb[tid] = bias[tid];
    __syncthreads();
    long gid = (long)blockIdx.x * 256 + tid;         // over B*T*32
    int c2 = (int)(gid & 31) * 2;
    long bt = gid >> 5;
    const float* ip = inp + bt * FIN;
    float a0 = sb[c2], a1 = sb[c2 + 1];
#pragma unroll
    for (int f = 0; f < FIN; f++) {
        float v = ip[f];
        a0 = fmaf(v, sw[f * 64 + c2], a0);
        a1 = fmaf(v, sw[f * 64 + c2 + 1], a1);
    }
    __nv_bfloat16 h0, l0, h1, l1;
    bsplit(a0, h0, l0);
    bsplit(a1, h1, l1);
    uint32_t hp = ((uint32_t)__bfloat16_as_ushort(h1) << 16) | (uint32_t)__bfloat16_as_ushort(h0);
    uint32_t lp = ((uint32_t)__bfloat16_as_ushort(l1) << 16) | (uint32_t)__bfloat16_as_ushort(l0);
    long oa = bt * 64 + c2;
    *reinterpret_cast<uint32_t*>(&xnh[oa]) = hp;
    *reinterpret_cast<uint32_t*>(&xnl[oa]) = lp;
}

// ---------------------------------------------------------------------------
// DFT: per CTA (s,b): D[128,64] += Fstack(128 x 1024) * x(1024 x 64).
// 2-stage cp.async pipeline, 64KB smem -> 3 CTAs/SM (24 warps: the
// occupancy experiment). Fl x xl term dropped; bands interleaved per SMSP.
#define DFT_STAGE_BYTES 32768
#define DFT_SMEM_BYTES (2 * DFT_STAGE_BYTES)
__global__ void __launch_bounds__(256) dft_mma(const __nv_bfloat16* __restrict__ xh,
                                               const __nv_bfloat16* __restrict__ xl) {
    extern __shared__ __align__(16) char sm[];
    int tid = threadIdx.x, lane = tid & 31, wid = tid >> 5;
    int warpm = wid >> 1, warpn = wid & 1;
    bool fullw = (warpm < 2);
    int s = blockIdx.x, b = blockIdx.y;
    float acc[2][4][4] = {};
    uint32_t smu = smem_u32(sm);
    const __nv_bfloat16* xhb = xh + (long)b * TT * 64;
    const __nv_bfloat16* xlb = xl + (long)b * TT * 64;

    auto issue = [&](int st, int it) {
        int tbase = s * KCHUNK + it * 64;
        uint32_t sA = smu + (uint32_t)st * DFT_STAGE_BYTES;
        uint32_t sBh = sA + 128 * 128;
        uint32_t sBl = sBh + 64 * 128;
#pragma unroll
        for (int j = 0; j < 4; j++) {
            int i = tid + j * 256;
            int r = i >> 3, c8 = i & 7;
            cpa16(sA + swz(r, c8), &g_Fbf[(long)r * TT + tbase + c8 * 8]);
        }
#pragma unroll
        for (int j = 0; j < 2; j++) {
            int i = tid + j * 256;
            int r = i >> 3, c8 = i & 7;
            long ga = (long)(tbase + r) * 64 + c8 * 8;
            cpa16(sBh + swz(r, c8), &xhb[ga]);
            cpa16(sBl + swz(r, c8), &xlb[ga]);
        }
    };

    issue(0, 0); CP_COMMIT();

    for (int it = 0; it < NITER; it++) {
        int cur = it & 1;
        if (it + 1 < NITER) issue(cur ^ 1, it + 1);
        CP_COMMIT();
        CP_WAIT(1);
        __syncthreads();

        uint32_t sA = smu + (uint32_t)cur * DFT_STAGE_BYTES;
        uint32_t sBh = sA + 128 * 128;
        uint32_t sBl = sBh + 64 * 128;
#pragma unroll
        for (int kk = 0; kk < 4; kk++) {
            uint32_t afr[2][4];
#pragma unroll
            for (int mt = 0; mt < 2; mt++) {
                int row = warpm * 32 + mt * 16 + (lane & 15);
                ldmA(afr[mt], sA + swz(row, kk * 2 + (lane >> 4)));
            }
#pragma unroll
            for (int ntp = 0; ntp < 2; ntp++) {
                int brow = kk * 16 + (lane & 15);
                int bchunk = warpn * 4 + ntp * 2 + (lane >> 4);
                uint32_t bh[4], bl[4];
                ldmB4(bh, sBh + swz(brow, bchunk));
                if (fullw) ldmB4(bl, sBl + swz(brow, bchunk));
#pragma unroll
                for (int mt = 0; mt < 2; mt++) {
                    mma16816(acc[mt][ntp * 2 + 0], afr[mt], bh + 0);
                    mma16816(acc[mt][ntp * 2 + 1], afr[mt], bh + 2);
                    if (fullw) {
                        mma16816(acc[mt][ntp * 2 + 0], afr[mt], bl + 0);
                        mma16816(acc[mt][ntp * 2 + 1], afr[mt], bl + 2);
                    }
                }
            }
        }
        __syncthreads();   // protect stage `cur` before it is re-issued at it+2
    }

    int g = lane >> 2, t4 = lane & 3;
    float* xp = g_Xp + ((long)s * BB + b) * 128 * 64;
#pragma unroll
    for (int mt = 0; mt < 2; mt++)
#pragma unroll
        for (int nt = 0; nt < 4; nt++) {
            int r = warpm * 32 + mt * 16 + g;
            int c = warpn * 32 + nt * 8 + t4 * 2;
            *reinterpret_cast<float2*>(&xp[(long)r * 64 + c]) =
                make_float2(acc[mt][nt][0], acc[mt][nt][1]);
            *reinterpret_cast<float2*>(&xp[(long)(r + 8) * 64 + c]) =
                make_float2(acc[mt][nt][2], acc[mt][nt][3]);
        }
}

// ---------------------------------------------------------------------------
// mix: 256 threads, 4 modes per block.
__global__ void __launch_bounds__(256) mix_k(const float* __restrict__ wr,
                                             const float* __restrict__ wi) {
    int kq = threadIdx.x >> 6;
    int k = blockIdx.x * 4 + kq;
    int b = blockIdx.y;
    int o = threadIdx.x & 63;
    __shared__ float sXr[4][64], sXi[4][64];
    float xr = 0.f, xi = 0.f;
#pragma unroll
    for (int s = 0; s < KSPLIT; s++) {
        const float* xp = g_Xp + ((long)s * BB + b) * 128 * 64;
        xr += xp[k * 64 + o] + xp[(64 + k) * 64 + o];
        xi += xp[(32 + k) * 64 + o] + xp[(96 + k) * 64 + o];
    }
    sXr[kq][o] = xr;
    sXi[kq][o] = xi;
    __syncthreads();
    float yr = 0.f, yi = 0.f;
    const float* wrk = wr + k * 64 * 64;
    const float* wik = wi + k * 64 * 64;
#pragma unroll 8
    for (int c = 0; c < 64; c++) {
        float wrv = wrk[c * 64 + o], wiv = wik[c * 64 + o];
        float cr = sXr[kq][c], ci = sXi[kq][c];
        yr = fmaf(cr, wrv, yr); yr = fmaf(-ci, wiv, yr);
        yi = fmaf(cr, wiv, yi); yi = fmaf(ci, wrv, yi);
    }
    const float inv = 1.0f / (float)TT;
    float zc, zs;
    if (k == 0) { zc = yr * inv; zs = 0.f; }
    else        { zc = yr * (2.0f * inv); zs = -yi * (2.0f * inv); }
    __nv_bfloat16 h, l;
    bsplit(zc, h, l);
    g_Zh[((long)b * 64 + k) * 64 + o] = h;
    g_Zl[((long)b * 64 + k) * 64 + o] = l;
    bsplit(zs, h, l);
    g_Zh[((long)b * 64 + 32 + k) * 64 + o] = h;
    g_Zl[((long)b * 64 + 32 + k) * 64 + o] = l;
}

// ---------------------------------------------------------------------------
// pw: fused irfft + conv + bias + GELU (R14 structure, unchanged).
#define PW_SMEM_BYTES ((4 * 128 * DPAD + 4 * 64 * DPAD) * 2)
__global__ void __launch_bounds__(256) pw_mma(const __nv_bfloat16* __restrict__ xh_in,
                                              const __nv_bfloat16* __restrict__ xl_in,
                                              const __nv_bfloat16* __restrict__ Zh,
                                              const __nv_bfloat16* __restrict__ Zl,
                                              const __nv_bfloat16* __restrict__ Cwh,
                                              const __nv_bfloat16* __restrict__ Cwl,
                                              const float* __restrict__ convb,
                                              __nv_bfloat16* __restrict__ xh_out,
                                              __nv_bfloat16* __restrict__ xl_out) {
    extern __shared__ __align__(16) __nv_bfloat16 smp[];
    __nv_bfloat16* sGh = smp;
    __nv_bfloat16* sGl = smp + 128 * DPAD;
    __nv_bfloat16* sXh = smp + 2 * 128 * DPAD;
    __nv_bfloat16* sXl = smp + 3 * 128 * DPAD;
    __nv_bfloat16* sZh = smp + 4 * 128 * DPAD;
    __nv_bfloat16* sZl = sZh + 64 * DPAD;
    __nv_bfloat16* sCh = sZh + 2 * 64 * DPAD;
    __nv_bfloat16* sCl = sZh + 3 * 64 * DPAD;
    int tid = threadIdx.x, lane = tid & 31, wid = tid >> 5;
    int warpm = wid & 3, warpn = wid >> 2;
    int t0 = blockIdx.x * 128, b = blockIdx.y;

    {
        const __nv_bfloat16* aGh = g_Gh + (long)t0 * 64;
        const __nv_bfloat16* aGl = g_Gl + (long)t0 * 64;
        const __nv_bfloat16* aXh = xh_in + ((long)b * TT + t0) * 64;
        const __nv_bfloat16* aXl = xl_in + ((long)b * TT + t0) * 64;
#pragma unroll
        for (int j = 0; j < 4; j++) {
            int i = tid + j * 256;
            int r = i >> 3, c8 = (i & 7) * 8;
            uint32_t so = smem_u32(smp) + (uint32_t)(r * DPAD + c8) * 2;
            long go = (long)r * 64 + c8;
            cpa16(so, &aGh[go]);
            cpa16(so + 128 * DPAD * 2, &aGl[go]);
            cpa16(so + 2 * 128 * DPAD * 2, &aXh[go]);
            cpa16(so + 3 * 128 * DPAD * 2, &aXl[go]);
        }
        const __nv_bfloat16* bZh = Zh + (long)b * 4096;
        const __nv_bfloat16* bZl = Zl + (long)b * 4096;
#pragma unroll
        for (int j = 0; j < 2; j++) {
            int i = tid + j * 256;
            int r = i >> 3, c8 = (i & 7) * 8;
            uint32_t so = smem_u32(sZh) + (uint32_t)(r * DPAD + c8) * 2;
            long go = (long)r * 64 + c8;
            cpa16(so, &bZh[go]);
            cpa16(so + 64 * DPAD * 2, &bZl[go]);
            cpa16(so + 2 * 64 * DPAD * 2, &Cwh[go]);
            cpa16(so + 3 * 64 * DPAD * 2, &Cwl[go]);
        }
        CP_COMMIT();
        CP_WAIT(0);
    }
    __syncthreads();

    uint32_t Au[4] = {smem_u32(sGh), smem_u32(sGl), smem_u32(sXh), smem_u32(sXl)};
    uint32_t Bu[4][2] = {{smem_u32(sZh), smem_u32(sZl)},
                         {smem_u32(sZh), 0},
                         {smem_u32(sCh), smem_u32(sCl)},
                         {smem_u32(sCh), 0}};
    const int nB[4] = {2, 1, 2, 1};
    float acc[2][4][4] = {};
#pragma unroll
    for (int ai = 0; ai < 4; ai++) {
#pragma unroll
        for (int kk = 0; kk < 4; kk++) {
            uint32_t afr[2][4];
#pragma unroll
            for (int mt = 0; mt < 2; mt++)
                ldmA(afr[mt], Au[ai] + (uint32_t)((warpm * 32 + mt * 16 + (lane & 15)) * DPAD
                                                  + kk * 16 + (lane >> 4) * 8) * 2);
#pragma unroll
            for (int bi = 0; bi < 2; bi++) {
                if (bi >= nB[ai]) break;
#pragma unroll
                for (int ntp = 0; ntp < 2; ntp++) {
                    uint32_t bfr[4];
                    ldmB4(bfr, Bu[ai][bi] + (uint32_t)((kk * 16 + (lane & 15)) * DPAD
                                                       + warpn * 32 + ntp * 16 + (lane >> 4) * 8) * 2);
#pragma unroll
                    for (int mt = 0; mt < 2; mt++) {
                        mma16816(acc[mt][ntp * 2 + 0], afr[mt], bfr + 0);
                        mma16816(acc[mt][ntp * 2 + 1], afr[mt], bfr + 2);
                    }
                }
            }
        }
    }

    int g = lane >> 2, t4 = lane & 3;
#pragma unroll
    for (int mt = 0; mt < 2; mt++)
#pragma unroll
        for (int nt = 0; nt < 4; nt++) {
            int r = warpm * 32 + mt * 16 + g;
            int c = warpn * 32 + nt * 8 + t4 * 2;
            float bc0 = convb[c], bc1 = convb[c + 1];
#pragma unroll
            for (int half = 0; half < 2; half++) {
                int rr = r + half * 8;
                float v0 = gelu_exact(acc[mt][nt][half * 2 + 0] + bc0);
                float v1 = gelu_exact(acc[mt][nt][half * 2 + 1] + bc1);
                __nv_bfloat16 h0, l0, h1, l1;
                bsplit(v0, h0, l0);
                bsplit(v1, h1, l1);
                uint32_t hp = ((uint32_t)__bfloat16_as_ushort(h1) << 16) |
                              (uint32_t)__bfloat16_as_ushort(h0);
                uint32_t lp = ((uint32_t)__bfloat16_as_ushort(l1) << 16) |
                              (uint32_t)__bfloat16_as_ushort(l0);
                long oa = ((long)b * TT + t0 + rr) * 64 + c;
                *reinterpret_cast<uint32_t*>(&xh_out[oa]) = hp;
                *reinterpret_cast<uint32_t*>(&xl_out[oa]) = lp;
            }
        }
}

// ---------------------------------------------------------------------------
__global__ void final_k(const __nv_bfloat16* __restrict__ xnh,
                        const __nv_bfloat16* __restrict__ xnl,
                        const float* __restrict__ convw,
                        const float* __restrict__ convb,
                        const float* __restrict__ fc1w,
                        const float* __restrict__ fc1b,
                        const float* __restrict__ fc2w,
                        const float* __restrict__ fc2b,
                        float* __restrict__ out) {
    int b = blockIdx.x;
    int tid = threadIdx.x;
    __shared__ float x4[64];
    __shared__ float h[NFC1];
    __shared__ float grow[64], xrow[64];
    if (tid < 64) {
        int j = tid;
        grow[j] = __bfloat162float(g_Gh[(long)(TT - 1) * 64 + j]) +
                  __bfloat162float(g_Gl[(long)(TT - 1) * 64 + j]);
        long xa = ((long)b * TT + (TT - 1)) * 64 + j;
        xrow[j] = __bfloat162float(xnh[xa]) + __bfloat162float(xnl[xa]);
    }
    __syncthreads();
    if (tid < 64) {
        int c = tid;
        float pre = convb[c];
        const __nv_bfloat16* zh = g_Zh + (long)b * 4096;
        const __nv_bfloat16* zl = g_Zl + (long)b * 4096;
#pragma unroll 8
        for (int j = 0; j < 64; j++) {
            float z = __bfloat162float(zh[j * 64 + c]) + __bfloat162float(zl[j * 64 + c]);
            pre = fmaf(grow[j], z, pre);
            pre = fmaf(xrow[j], convw[j * 64 + c], pre);
        }
        x4[c] = gelu_exact(pre);
    }
    __syncthreads();
    {
        float acc = fc1b[tid];
#pragma unroll 8
        for (int c = 0; c < 64; c++) acc = fmaf(x4[c], fc1w[c * NFC1 + tid], acc);
        h[tid] = gelu_exact(acc);
    }
    __syncthreads();
    if (tid < NOUT) {
        float acc = fc2b[tid];
#pragma unroll 8
        for (int f = 0; f < NFC1; f++) acc = fmaf(h[f], fc2w[f * NOUT + tid], acc);
        out[b * NOUT + tid] = acc;
    }
}

// ---------------------------------------------------------------------------
extern "C" void kernel_launch(void* const* d_in, const int* in_sizes, int n_in,
                              void* d_out, int out_size) {
    const float* inputs = (const float*)d_in[0];
    const float* fc0_w  = (const float*)d_in[1];
    const float* fc0_b  = (const float*)d_in[2];
    const float* fwr    = (const float*)d_in[3];
    const float* fwi    = (const float*)d_in[4];
    const float* convw  = (const float*)d_in[5];
    const float* convb  = (const float*)d_in[6];
    const float* fc1w   = (const float*)d_in[7];
    const float* fc1b   = (const float*)d_in[8];
    const float* fc2w   = (const float*)d_in[9];
    const float* fc2b   = (const float*)d_in[10];
    float* out = (float*)d_out;

    cudaFuncSetAttribute(pw_mma, cudaFuncAttributeMaxDynamicSharedMemorySize, PW_SMEM_BYTES);
    cudaFuncSetAttribute(dft_mma, cudaFuncAttributeMaxDynamicSharedMemorySize, DFT_SMEM_BYTES);

    __nv_bfloat16 *xnh0, *xnl0, *zh, *zl, *cwh, *cwl;
    cudaGetSymbolAddress((void**)&xnh0, g_xnh);
    cudaGetSymbolAddress((void**)&xnl0, g_xnl);
    cudaGetSymbolAddress((void**)&zh, g_Zh);
    cudaGetSymbolAddress((void**)&zl, g_Zl);
    cudaGetSymbolAddress((void**)&cwh, g_cwh);
    cudaGetSymbolAddress((void**)&cwl, g_cwl);
    __nv_bfloat16* xnh1 = xnh0 + XELEMS;
    __nv_bfloat16* xnl1 = xnl0 + XELEMS;

    twiddle_k<<<(MODES * TT + 255) / 256, 256>>>();
    cwprep<<<(NLAYERS * 64 * 64 + 255) / 256, 256>>>(convw);
    fc0_bf<<<(int)(((long)BB * TT * 32) / 256), 256>>>(inputs, fc0_w, fc0_b, xnh0, xnl0);

    __nv_bfloat16 *cnh = xnh0, *cnl = xnl0, *nnh = xnh1, *nnl = xnl1;
    for (int l = 0; l < NLAYERS; l++) {
        dft_mma<<<dim3(KSPLIT, BB), 256, DFT_SMEM_BYTES>>>(cnh, cnl);
        mix_k<<<dim3(MODES / 4, BB), 256>>>(fwr + (long)l * MODES * 64 * 64,
                                            fwi + (long)l * MODES * 64 * 64);
        if (l < NLAYERS - 1) {
            pw_mma<<<dim3(TT / 128, BB), 256, PW_SMEM_BYTES>>>(
                cnh, cnl, zh, zl, cwh + (long)l * 4096, cwl + (long)l * 4096,
                convb + (long)l * 64, nnh, nnl);
            __nv_bfloat16* t;
            t = cnh; cnh = nnh; nnh = t;
            t = cnl; cnl = nnl; nnl = t;
        } else {
            final_k<<<BB, 128>>>(cnh, cnl, convw + (long)l * 4096, convb + (long)l * 64,
                                 fc1w, fc1b, fc2w, fc2b, out);
        }
    }
}